// round 13
// baseline (speedup 1.0000x reference)
#include <cuda_runtime.h>
#include <cuda_fp16.h>
#include <stdint.h>
#include <math.h>

typedef __half fp16;

#define BB 8
#define SEQ 2048
#define DDIM 1024
#define MTOT (BB * SEQ)   // 16384

// ------------------------------------------------------------------
// PTX helpers (sm_80+ features only)
// ------------------------------------------------------------------
__device__ __forceinline__ uint32_t smem_u32(const void* p) {
    uint32_t a;
    asm("{ .reg .u64 t; cvta.to.shared.u64 t, %1; cvt.u32.u64 %0, t; }"
        : "=r"(a) : "l"(p));
    return a;
}
#define CP16(dst, src) \
    asm volatile("cp.async.cg.shared.global [%0], [%1], 16;" :: "r"(dst), "l"(src))
#define CP_COMMIT() asm volatile("cp.async.commit_group;" ::: "memory")
#define CP_WAIT1()  asm volatile("cp.async.wait_group 1;" ::: "memory")

__device__ __forceinline__ void ldmx4(uint32_t* r, uint32_t addr) {
    asm volatile("ldmatrix.sync.aligned.m8n8.x4.shared.b16 {%0,%1,%2,%3}, [%4];"
        : "=r"(r[0]), "=r"(r[1]), "=r"(r[2]), "=r"(r[3]) : "r"(addr));
}
__device__ __forceinline__ void mma16816(float* c, const uint32_t* a, const uint32_t* b) {
    asm("mma.sync.aligned.m16n8k16.row.col.f32.f16.f16.f32 "
        "{%0,%1,%2,%3}, {%4,%5,%6,%7}, {%8,%9}, {%0,%1,%2,%3};"
        : "+f"(c[0]), "+f"(c[1]), "+f"(c[2]), "+f"(c[3])
        : "r"(a[0]), "r"(a[1]), "r"(a[2]), "r"(a[3]), "r"(b[0]), "r"(b[1]));
}

// ------------------------------------------------------------------
// Scratch (static device globals; allocation forbidden)
// ------------------------------------------------------------------
__device__ fp16 g_iqh[(size_t)MTOT * DDIM], g_iql[(size_t)MTOT * DDIM];
__device__ fp16 g_ikh[(size_t)MTOT * DDIM], g_ikl[(size_t)MTOT * DDIM];
__device__ fp16 g_ivh[(size_t)MTOT * DDIM];
__device__ fp16 g_wt[5][2][(size_t)DDIM * DDIM];
__device__ fp16 g_qh[(size_t)MTOT * DDIM], g_ql[(size_t)MTOT * DDIM];
__device__ fp16 g_kh[(size_t)MTOT * DDIM], g_kl[(size_t)MTOT * DDIM];
__device__ fp16 g_v16[(size_t)MTOT * DDIM];
__device__ fp16 g_vth[(size_t)BB * DDIM * SEQ];
__device__ fp16 g_gate16[(size_t)MTOT * DDIM];
__device__ float g_sc[(size_t)BB * SEQ * SEQ];
__device__ fp16 g_ph[(size_t)BB * SEQ * SEQ];
__device__ fp16 g_ch[(size_t)MTOT * DDIM];

// ------------------------------------------------------------------
// Elementwise split: fp32 -> hi(fp16), lo(fp16)
// ------------------------------------------------------------------
__global__ __launch_bounds__(256)
void split_f32(const float* __restrict__ x, fp16* __restrict__ h,
               fp16* __restrict__ l, size_t n)
{
    size_t i = ((size_t)blockIdx.x * 256 + threadIdx.x) * 4;
    if (i >= n) return;
    float4 v = *(const float4*)(x + i);
    fp16 h0 = __float2half(v.x), h1 = __float2half(v.y);
    fp16 h2 = __float2half(v.z), h3 = __float2half(v.w);
    __half2 hh0, hh1, ll0, ll1;
    hh0.x = h0; hh0.y = h1; hh1.x = h2; hh1.y = h3;
    ll0.x = __float2half(v.x - __half2float(h0));
    ll0.y = __float2half(v.y - __half2float(h1));
    ll1.x = __float2half(v.z - __half2float(h2));
    ll1.y = __float2half(v.w - __half2float(h3));
    *(__half2*)(h + i)     = hh0;
    *(__half2*)(h + i + 2) = hh1;
    *(__half2*)(l + i)     = ll0;
    *(__half2*)(l + i + 2) = ll1;
}

// ------------------------------------------------------------------
// Elementwise convert: fp32 -> fp16 (hi only)
// ------------------------------------------------------------------
__global__ __launch_bounds__(256)
void conv_f16(const float* __restrict__ x, fp16* __restrict__ h, size_t n)
{
    size_t i = ((size_t)blockIdx.x * 256 + threadIdx.x) * 4;
    if (i >= n) return;
    float4 v = *(const float4*)(x + i);
    __half2 a, b;
    a.x = __float2half(v.x); a.y = __float2half(v.y);
    b.x = __float2half(v.z); b.y = __float2half(v.w);
    *(__half2*)(h + i)     = a;
    *(__half2*)(h + i + 2) = b;
}

// ------------------------------------------------------------------
// Transpose + split: src [R,C] fp32 -> dst [C,R] hi/lo fp16 (weights)
// ------------------------------------------------------------------
__global__ __launch_bounds__(256)
void transpose_split(const float* __restrict__ src, fp16* __restrict__ dh,
                     fp16* __restrict__ dl, int R, int C)
{
    __shared__ float t[32][33];
    int r0 = blockIdx.y * 32, c0 = blockIdx.x * 32;
#pragma unroll
    for (int i = 0; i < 32; i += 8)
        t[threadIdx.y + i][threadIdx.x] =
            src[(size_t)(r0 + threadIdx.y + i) * C + c0 + threadIdx.x];
    __syncthreads();
#pragma unroll
    for (int i = 0; i < 32; i += 8) {
        int cc = c0 + threadIdx.y + i;
        int rr = r0 + threadIdx.x;
        float v = t[threadIdx.x][threadIdx.y + i];
        fp16 h = __float2half(v);
        dh[(size_t)cc * R + rr] = h;
        dl[(size_t)cc * R + rr] = __float2half(v - __half2float(h));
    }
}

// ------------------------------------------------------------------
// Transpose fp16 -> fp16: src [R,C] -> dst [C,R], batched
// ------------------------------------------------------------------
__global__ __launch_bounds__(256)
void transpose_h16(const fp16* __restrict__ src, fp16* __restrict__ dh,
                   int R, int C, long long sb, long long db)
{
    __shared__ fp16 t[32][34];
    src += (long long)blockIdx.z * sb;
    dh  += (long long)blockIdx.z * db;
    int r0 = blockIdx.y * 32, c0 = blockIdx.x * 32;
#pragma unroll
    for (int i = 0; i < 32; i += 8)
        t[threadIdx.y + i][threadIdx.x] =
            src[(size_t)(r0 + threadIdx.y + i) * C + c0 + threadIdx.x];
    __syncthreads();
#pragma unroll
    for (int i = 0; i < 32; i += 8) {
        int cc = c0 + threadIdx.y + i;
        int rr = r0 + threadIdx.x;
        dh[(size_t)cc * R + rr] = t[threadIdx.x][threadIdx.y + i];
    }
}

// ------------------------------------------------------------------
// Register-resident row softmax: one read + one fp16 write.
// ------------------------------------------------------------------
__global__ __launch_bounds__(256)
void softmax_p(const float* __restrict__ Sc, fp16* __restrict__ Ph)
{
    __shared__ float red[8];
    const size_t row = blockIdx.x;
    const int tid  = threadIdx.x;
    const int lane = tid & 31;
    const int wrp  = tid >> 5;
    const float* p = Sc + row * SEQ;

    float r[8];
#pragma unroll
    for (int i = 0; i < 8; i++) r[i] = p[tid + i * 256];

    float m = r[0];
#pragma unroll
    for (int i = 1; i < 8; i++) m = fmaxf(m, r[i]);
#pragma unroll
    for (int o = 16; o > 0; o >>= 1)
        m = fmaxf(m, __shfl_xor_sync(0xFFFFFFFFu, m, o));
    if (lane == 0) red[wrp] = m;
    __syncthreads();
    float gm = red[0];
#pragma unroll
    for (int j = 1; j < 8; j++) gm = fmaxf(gm, red[j]);
    __syncthreads();

    float s = 0.0f;
#pragma unroll
    for (int i = 0; i < 8; i++) { r[i] = __expf(r[i] - gm); s += r[i]; }
#pragma unroll
    for (int o = 16; o > 0; o >>= 1)
        s += __shfl_xor_sync(0xFFFFFFFFu, s, o);
    if (lane == 0) red[wrp] = s;
    __syncthreads();
    float gs = red[0];
#pragma unroll
    for (int j = 1; j < 8; j++) gs += red[j];
    float inv = 1.0f / gs;

#pragma unroll
    for (int i = 0; i < 8; i++)
        Ph[row * SEQ + tid + i * 256] = __float2half(r[i] * inv);
}

// ------------------------------------------------------------------
// mma.sync fp16 split-emulated GEMM: C[M,N] = A[M,K] @ B[N,K]^T (NT)
// 256 threads, 8 warps 4x2, warp tile 32x64, BK=64, 3 stages.
// mode 0: 3-pass A{hi,lo,hi} B{hi,hi,lo} | 1: A{hi,lo} B{hi,hi}
//      2: A{hi,hi} B{hi,lo}              | 3: 1-pass hi only
// epi: 0 fp32 raw | 1 bias fp32 | 2 bias+split hi/lo | 3 bias+sigmoid fp16
//      4 bias fp16 | 5 gate(fp16)*acc -> fp16
// pair=1: blockIdx.z==1 swaps in the "2" operand set (zb=0);
// pair=0: blockIdx.z is the batch index.
// ------------------------------------------------------------------
#define STAGES 3
#define STAGE_BYTES 32768
#define GEMM_SMEM (STAGES * STAGE_BYTES)

__global__ __launch_bounds__(256, 2)
void gemm3(const fp16* __restrict__ Ah, const fp16* __restrict__ Al,
           const fp16* __restrict__ Bh, const fp16* __restrict__ Bl,
           long long sAb, long long sBb, int K, int mode,
           float* __restrict__ Cf, fp16* __restrict__ Coh, fp16* __restrict__ Col,
           int ldc, long long sCb,
           const float* __restrict__ bias, const fp16* __restrict__ gateh,
           long long sGb, int epi,
           int pair,
           const fp16* __restrict__ Ah2, const fp16* __restrict__ Al2,
           const fp16* __restrict__ Bh2, const fp16* __restrict__ Bl2,
           fp16* __restrict__ Coh2, fp16* __restrict__ Col2,
           const float* __restrict__ bias2, int epi2)
{
    extern __shared__ char dsm[];
    const uint32_t sbase = smem_u32(dsm);

    const int tid  = threadIdx.x;
    const int wid  = tid >> 5;
    const int lane = tid & 31;
    const int wm = wid >> 1;          // 0..3
    const int wn = wid & 1;           // 0..1

    long long zb;
    int epiE = epi;
    if (pair) {
        zb = 0;
        if (blockIdx.z == 1) {
            Ah = Ah2; Al = Al2; Bh = Bh2; Bl = Bl2;
            Coh = Coh2; Col = Col2; bias = bias2; epiE = epi2;
        }
    } else {
        zb = (long long)blockIdx.z;
    }
    Ah += zb * sAb; Al += zb * sAb;
    Bh += zb * sBb; Bl += zb * sBb;

    const int m0 = blockIdx.y * 128;
    const int n0 = blockIdx.x * 128;
    const int KC = K >> 6;
    const int npass = (mode == 0) ? 3 : ((mode == 3) ? 1 : 2);
    const int NC = npass * KC;

    int rows[4], cols[4];
    uint32_t soff[4];
#pragma unroll
    for (int i = 0; i < 4; i++) {
        int idx = tid + i * 256;
        rows[i] = idx >> 3;
        cols[i] = idx & 7;
        soff[i] = (uint32_t)(rows[i] * 128 + ((cols[i] ^ (rows[i] & 7)) << 4));
    }

    auto load_chunk = [&](int c, int stage) {
        int phase = c / KC;
        int inner = c - phase * KC;
        const fp16* As = Ah;
        const fp16* Bs = Bh;
        if (mode == 0) {
            if (phase == 1) As = Al;
            if (phase == 2) Bs = Bl;
        } else if (mode == 1) {
            if (phase == 1) As = Al;
        } else if (mode == 2) {
            if (phase == 1) Bs = Bl;
        }
        uint32_t aB = sbase + (uint32_t)stage * STAGE_BYTES;
        uint32_t bB = aB + 16384u;
#pragma unroll
        for (int i = 0; i < 4; i++)
            CP16(aB + soff[i], As + (size_t)(m0 + rows[i]) * K + inner * 64 + cols[i] * 8);
#pragma unroll
        for (int i = 0; i < 4; i++)
            CP16(bB + soff[i], Bs + (size_t)(n0 + rows[i]) * K + inner * 64 + cols[i] * 8);
    };

    load_chunk(0, 0); CP_COMMIT();
    load_chunk(1, 1); CP_COMMIT();

    float acc[2][8][4];
#pragma unroll
    for (int mt = 0; mt < 2; mt++)
#pragma unroll
        for (int nt = 0; nt < 8; nt++)
#pragma unroll
            for (int r = 0; r < 4; r++) acc[mt][nt][r] = 0.0f;

    const int aRowBase = wm * 32 + (lane & 15);
    const int bRowBase = wn * 64 + (lane & 15);
    const int khalf    = lane >> 4;

    for (int c = 0; c < NC; c++) {
        const int st = c % STAGES;
        CP_WAIT1();
        __syncthreads();
        if (c + 2 < NC) load_chunk(c + 2, (c + 2) % STAGES);
        CP_COMMIT();
        const uint32_t aB = sbase + (uint32_t)st * STAGE_BYTES;
        const uint32_t bB = aB + 16384u;
#pragma unroll
        for (int ks = 0; ks < 4; ks++) {
            const int ch = 2 * ks + khalf;
            uint32_t afr[2][4];
#pragma unroll
            for (int mt = 0; mt < 2; mt++) {
                int r = aRowBase + mt * 16;
                ldmx4(afr[mt], aB + (uint32_t)(r * 128 + ((ch ^ (r & 7)) << 4)));
            }
            uint32_t bfr[8][2];
#pragma unroll
            for (int nb = 0; nb < 4; nb++) {
                int r = bRowBase + nb * 16;
                uint32_t t4[4];
                ldmx4(t4, bB + (uint32_t)(r * 128 + ((ch ^ (r & 7)) << 4)));
                bfr[nb * 2][0]     = t4[0];
                bfr[nb * 2][1]     = t4[2];
                bfr[nb * 2 + 1][0] = t4[1];
                bfr[nb * 2 + 1][1] = t4[3];
            }
#pragma unroll
            for (int mt = 0; mt < 2; mt++)
#pragma unroll
                for (int nt = 0; nt < 8; nt++)
                    mma16816(acc[mt][nt], afr[mt], bfr[nt]);
        }
    }

    // ---------------- epilogue ----------------
    const int erow0 = m0 + wm * 32 + (lane >> 2);
    const int ecol0 = n0 + wn * 64 + (lane & 3) * 2;

#pragma unroll
    for (int mt = 0; mt < 2; mt++) {
#pragma unroll
        for (int rr = 0; rr < 2; rr++) {
            const int row = erow0 + mt * 16 + rr * 8;
#pragma unroll
            for (int nt = 0; nt < 8; nt++) {
                const int col = ecol0 + nt * 8;
                float v0 = acc[mt][nt][2 * rr];
                float v1 = acc[mt][nt][2 * rr + 1];
                const size_t off = (size_t)zb * sCb + (size_t)row * ldc + col;
                if (epiE == 0) {
                    *(float2*)(Cf + off) = make_float2(v0, v1);
                } else if (epiE == 1) {
                    v0 += bias[col]; v1 += bias[col + 1];
                    *(float2*)(Cf + off) = make_float2(v0, v1);
                } else if (epiE == 3 || epiE == 4) {
                    v0 += bias[col]; v1 += bias[col + 1];
                    if (epiE == 3) {
                        v0 = 1.0f / (1.0f + __expf(-v0));
                        v1 = 1.0f / (1.0f + __expf(-v1));
                    }
                    __half2 hh;
                    hh.x = __float2half(v0);
                    hh.y = __float2half(v1);
                    *(__half2*)(Coh + off) = hh;
                } else if (epiE == 5) {
                    __half2 gg = *(const __half2*)(gateh + (size_t)zb * sGb +
                                                   (size_t)row * ldc + col);
                    __half2 hh;
                    hh.x = __float2half(v0 * __half2float(gg.x));
                    hh.y = __float2half(v1 * __half2float(gg.y));
                    *(__half2*)(Coh + off) = hh;
                } else { // epi 2: bias + split hi/lo
                    v0 += bias[col]; v1 += bias[col + 1];
                    fp16 h0 = __float2half(v0), h1 = __float2half(v1);
                    __half2 hh, ll;
                    hh.x = h0; hh.y = h1;
                    ll.x = __float2half(v0 - __half2float(h0));
                    ll.y = __float2half(v1 - __half2float(h1));
                    *(__half2*)(Coh + off) = hh;
                    *(__half2*)(Col + off) = ll;
                }
            }
        }
    }
}

// ------------------------------------------------------------------
// launch
// ------------------------------------------------------------------
extern "C" void kernel_launch(void* const* d_in, const int* in_sizes, int n_in,
                              void* d_out, int out_size)
{
    const float* queries = (const float*)d_in[0];
    const float* keys    = (const float*)d_in[1];
    const float* values  = (const float*)d_in[2];
    const float* Wq = (const float*)d_in[3];
    const float* bq = (const float*)d_in[4];
    const float* Wk = (const float*)d_in[5];
    const float* bk = (const float*)d_in[6];
    const float* Wv = (const float*)d_in[7];
    const float* bv = (const float*)d_in[8];
    const float* Wg = (const float*)d_in[9];
    const float* bg = (const float*)d_in[10];
    const float* Wo = (const float*)d_in[11];
    const float* bo = (const float*)d_in[12];
    float* out = (float*)d_out;

    fp16 *iqh, *iql, *ikh, *ikl, *ivh, *wt;
    fp16 *qh, *ql, *kh, *kl, *v16, *vth, *gate16, *ph, *ch;
    float *sc;
    cudaGetSymbolAddress((void**)&iqh, g_iqh); cudaGetSymbolAddress((void**)&iql, g_iql);
    cudaGetSymbolAddress((void**)&ikh, g_ikh); cudaGetSymbolAddress((void**)&ikl, g_ikl);
    cudaGetSymbolAddress((void**)&ivh, g_ivh);
    cudaGetSymbolAddress((void**)&wt,  g_wt);
    cudaGetSymbolAddress((void**)&qh,  g_qh);  cudaGetSymbolAddress((void**)&ql,  g_ql);
    cudaGetSymbolAddress((void**)&kh,  g_kh);  cudaGetSymbolAddress((void**)&kl,  g_kl);
    cudaGetSymbolAddress((void**)&v16, g_v16);
    cudaGetSymbolAddress((void**)&vth, g_vth);
    cudaGetSymbolAddress((void**)&gate16, g_gate16);
    cudaGetSymbolAddress((void**)&sc,  g_sc);
    cudaGetSymbolAddress((void**)&ph,  g_ph);
    cudaGetSymbolAddress((void**)&ch,  g_ch);

    const size_t WSZ = (size_t)DDIM * DDIM;
    fp16* wth[5]; fp16* wtl[5];
    for (int w = 0; w < 5; w++) { wth[w] = wt + (2*w)*WSZ; wtl[w] = wt + (2*w+1)*WSZ; }

    cudaFuncSetAttribute(gemm3, cudaFuncAttributeMaxDynamicSharedMemorySize, GEMM_SMEM);

    const size_t nElem = (size_t)MTOT * DDIM;
    const int splitBlocks = (int)(nElem / 1024);
    dim3 tb(32, 8);
    dim3 gp(DDIM / 128, MTOT / 128, 1);

    // prep (R11 structure)
    split_f32<<<splitBlocks, 256>>>(queries, iqh, iql, nElem);
    split_f32<<<splitBlocks, 256>>>(keys,    ikh, ikl, nElem);
    conv_f16<<<splitBlocks, 256>>>(values,  ivh, nElem);
    transpose_split<<<dim3(32, 32), tb>>>(Wq, wth[0], wtl[0], DDIM, DDIM);
    transpose_split<<<dim3(32, 32), tb>>>(Wk, wth[1], wtl[1], DDIM, DDIM);
    transpose_split<<<dim3(32, 32), tb>>>(Wv, wth[2], wtl[2], DDIM, DDIM);
    transpose_split<<<dim3(32, 32), tb>>>(Wg, wth[3], wtl[3], DDIM, DDIM);
    transpose_split<<<dim3(32, 32), tb>>>(Wo, wth[4], wtl[4], DDIM, DDIM);

    // q + k projections — 3-pass, merged via pair (z=0: q, z=1: k)
    gemm3<<<dim3(DDIM / 128, MTOT / 128, 2), 256, GEMM_SMEM>>>(
        iqh, iql, wth[0], wtl[0], 0, 0, DDIM, 0,
        nullptr, qh, ql, DDIM, 0, bq, nullptr, 0, 2,
        1, ikh, ikl, wth[1], wtl[1], kh, kl, bk, 2);

    // v + gate projections — 1-pass, merged (z=0: v->fp16, z=1: gate sigmoid)
    gemm3<<<dim3(DDIM / 128, MTOT / 128, 2), 256, GEMM_SMEM>>>(
        ivh, ivh, wth[2], wth[2], 0, 0, DDIM, 3,
        nullptr, v16, nullptr, DDIM, 0, bv, nullptr, 0, 4,
        1, iqh, iqh, wth[3], wth[3], gate16, nullptr, bg, 3);

    // scores = q @ k^T (per batch) — 3-pass
    gemm3<<<dim3(SEQ / 128, SEQ / 128, BB), 256, GEMM_SMEM>>>(
        qh, ql, kh, kl, (long long)SEQ * DDIM, (long long)SEQ * DDIM, DDIM, 0,
        sc, nullptr, nullptr, SEQ, (long long)SEQ * SEQ, nullptr, nullptr, 0, 0,
        0, nullptr, nullptr, nullptr, nullptr, nullptr, nullptr, nullptr, 0);

    // softmax -> fp16 P
    softmax_p<<<MTOT, 256>>>(sc, ph);

    // transpose v per batch: fp16 [S,D] -> [D,S]
    transpose_h16<<<dim3(DDIM / 32, SEQ / 32, BB), tb>>>(
        v16, vth, SEQ, DDIM, (long long)SEQ * DDIM, (long long)SEQ * DDIM);

    // context = (P @ v) * gate -> fp16; 1-pass
    gemm3<<<dim3(DDIM / 128, SEQ / 128, BB), 256, GEMM_SMEM>>>(
        ph, ph, vth, vth, (long long)SEQ * SEQ, (long long)DDIM * SEQ, SEQ, 3,
        nullptr, ch, nullptr, DDIM, (long long)SEQ * DDIM,
        nullptr, gate16, (long long)SEQ * DDIM, 5,
        0, nullptr, nullptr, nullptr, nullptr, nullptr, nullptr, nullptr, 0);

    // out = ctx @ Wo + bo — 1-pass
    gemm3<<<gp, 256, GEMM_SMEM>>>(
        ch, ch, wth[4], wth[4], 0, 0, DDIM, 3,
        out, nullptr, nullptr, DDIM, 0, bo, nullptr, 0, 1,
        0, nullptr, nullptr, nullptr, nullptr, nullptr, nullptr, nullptr, 0);
}

// round 14
// speedup vs baseline: 1.0811x; 1.0811x over previous
#include <cuda_runtime.h>
#include <cuda_fp16.h>
#include <stdint.h>
#include <math.h>

typedef __half fp16;

#define BB 8
#define SEQ 2048
#define DDIM 1024
#define MTOT (BB * SEQ)   // 16384

// ------------------------------------------------------------------
// PTX helpers (sm_80+ features only)
// ------------------------------------------------------------------
__device__ __forceinline__ uint32_t smem_u32(const void* p) {
    uint32_t a;
    asm("{ .reg .u64 t; cvta.to.shared.u64 t, %1; cvt.u32.u64 %0, t; }"
        : "=r"(a) : "l"(p));
    return a;
}
#define CP16(dst, src) \
    asm volatile("cp.async.cg.shared.global [%0], [%1], 16;" :: "r"(dst), "l"(src))
#define CP_COMMIT() asm volatile("cp.async.commit_group;" ::: "memory")
#define CP_WAIT1()  asm volatile("cp.async.wait_group 1;" ::: "memory")

__device__ __forceinline__ void ldmx4(uint32_t* r, uint32_t addr) {
    asm volatile("ldmatrix.sync.aligned.m8n8.x4.shared.b16 {%0,%1,%2,%3}, [%4];"
        : "=r"(r[0]), "=r"(r[1]), "=r"(r[2]), "=r"(r[3]) : "r"(addr));
}
__device__ __forceinline__ void mma16816(float* c, const uint32_t* a, const uint32_t* b) {
    asm("mma.sync.aligned.m16n8k16.row.col.f32.f16.f16.f32 "
        "{%0,%1,%2,%3}, {%4,%5,%6,%7}, {%8,%9}, {%0,%1,%2,%3};"
        : "+f"(c[0]), "+f"(c[1]), "+f"(c[2]), "+f"(c[3])
        : "r"(a[0]), "r"(a[1]), "r"(a[2]), "r"(a[3]), "r"(b[0]), "r"(b[1]));
}

// ------------------------------------------------------------------
// Scratch (static device globals; allocation forbidden)
// ------------------------------------------------------------------
__device__ fp16 g_iqh[(size_t)MTOT * DDIM], g_iql[(size_t)MTOT * DDIM];
__device__ fp16 g_ikh[(size_t)MTOT * DDIM], g_ikl[(size_t)MTOT * DDIM];
__device__ fp16 g_ivh[(size_t)MTOT * DDIM];
__device__ fp16 g_wt[5][2][(size_t)DDIM * DDIM];
__device__ fp16 g_qh[(size_t)MTOT * DDIM], g_ql[(size_t)MTOT * DDIM];
__device__ fp16 g_kh[(size_t)MTOT * DDIM], g_kl[(size_t)MTOT * DDIM];
__device__ fp16 g_v16[(size_t)MTOT * DDIM];
__device__ fp16 g_vth[(size_t)BB * DDIM * SEQ];
__device__ fp16 g_gate16[(size_t)MTOT * DDIM];
__device__ float g_sc[(size_t)BB * SEQ * SEQ];
__device__ fp16 g_ph[(size_t)BB * SEQ * SEQ];
__device__ fp16 g_ch[(size_t)MTOT * DDIM];

// ------------------------------------------------------------------
// Elementwise split: fp32 -> hi(fp16), lo(fp16)
// ------------------------------------------------------------------
__global__ __launch_bounds__(256)
void split_f32(const float* __restrict__ x, fp16* __restrict__ h,
               fp16* __restrict__ l, size_t n)
{
    size_t i = ((size_t)blockIdx.x * 256 + threadIdx.x) * 4;
    if (i >= n) return;
    float4 v = *(const float4*)(x + i);
    fp16 h0 = __float2half(v.x), h1 = __float2half(v.y);
    fp16 h2 = __float2half(v.z), h3 = __float2half(v.w);
    __half2 hh0, hh1, ll0, ll1;
    hh0.x = h0; hh0.y = h1; hh1.x = h2; hh1.y = h3;
    ll0.x = __float2half(v.x - __half2float(h0));
    ll0.y = __float2half(v.y - __half2float(h1));
    ll1.x = __float2half(v.z - __half2float(h2));
    ll1.y = __float2half(v.w - __half2float(h3));
    *(__half2*)(h + i)     = hh0;
    *(__half2*)(h + i + 2) = hh1;
    *(__half2*)(l + i)     = ll0;
    *(__half2*)(l + i + 2) = ll1;
}

// ------------------------------------------------------------------
// Elementwise convert: fp32 -> fp16 (hi only)
// ------------------------------------------------------------------
__global__ __launch_bounds__(256)
void conv_f16(const float* __restrict__ x, fp16* __restrict__ h, size_t n)
{
    size_t i = ((size_t)blockIdx.x * 256 + threadIdx.x) * 4;
    if (i >= n) return;
    float4 v = *(const float4*)(x + i);
    __half2 a, b;
    a.x = __float2half(v.x); a.y = __float2half(v.y);
    b.x = __float2half(v.z); b.y = __float2half(v.w);
    *(__half2*)(h + i)     = a;
    *(__half2*)(h + i + 2) = b;
}

// ------------------------------------------------------------------
// Transpose + split: src [R,C] fp32 -> dst [C,R] hi/lo fp16 (weights)
// ------------------------------------------------------------------
__global__ __launch_bounds__(256)
void transpose_split(const float* __restrict__ src, fp16* __restrict__ dh,
                     fp16* __restrict__ dl, int R, int C)
{
    __shared__ float t[32][33];
    int r0 = blockIdx.y * 32, c0 = blockIdx.x * 32;
#pragma unroll
    for (int i = 0; i < 32; i += 8)
        t[threadIdx.y + i][threadIdx.x] =
            src[(size_t)(r0 + threadIdx.y + i) * C + c0 + threadIdx.x];
    __syncthreads();
#pragma unroll
    for (int i = 0; i < 32; i += 8) {
        int cc = c0 + threadIdx.y + i;
        int rr = r0 + threadIdx.x;
        float v = t[threadIdx.x][threadIdx.y + i];
        fp16 h = __float2half(v);
        dh[(size_t)cc * R + rr] = h;
        dl[(size_t)cc * R + rr] = __float2half(v - __half2float(h));
    }
}

// ------------------------------------------------------------------
// Transpose fp16 -> fp16: src [R,C] -> dst [C,R], batched
// ------------------------------------------------------------------
__global__ __launch_bounds__(256)
void transpose_h16(const fp16* __restrict__ src, fp16* __restrict__ dh,
                   int R, int C, long long sb, long long db)
{
    __shared__ fp16 t[32][34];
    src += (long long)blockIdx.z * sb;
    dh  += (long long)blockIdx.z * db;
    int r0 = blockIdx.y * 32, c0 = blockIdx.x * 32;
#pragma unroll
    for (int i = 0; i < 32; i += 8)
        t[threadIdx.y + i][threadIdx.x] =
            src[(size_t)(r0 + threadIdx.y + i) * C + c0 + threadIdx.x];
    __syncthreads();
#pragma unroll
    for (int i = 0; i < 32; i += 8) {
        int cc = c0 + threadIdx.y + i;
        int rr = r0 + threadIdx.x;
        dh[(size_t)cc * R + rr] = t[threadIdx.x][threadIdx.y + i];
    }
}

// ------------------------------------------------------------------
// Register-resident row softmax: one read + one fp16 write.
// ------------------------------------------------------------------
__global__ __launch_bounds__(256)
void softmax_p(const float* __restrict__ Sc, fp16* __restrict__ Ph)
{
    __shared__ float red[8];
    const size_t row = blockIdx.x;
    const int tid  = threadIdx.x;
    const int lane = tid & 31;
    const int wrp  = tid >> 5;
    const float* p = Sc + row * SEQ;

    float r[8];
#pragma unroll
    for (int i = 0; i < 8; i++) r[i] = p[tid + i * 256];

    float m = r[0];
#pragma unroll
    for (int i = 1; i < 8; i++) m = fmaxf(m, r[i]);
#pragma unroll
    for (int o = 16; o > 0; o >>= 1)
        m = fmaxf(m, __shfl_xor_sync(0xFFFFFFFFu, m, o));
    if (lane == 0) red[wrp] = m;
    __syncthreads();
    float gm = red[0];
#pragma unroll
    for (int j = 1; j < 8; j++) gm = fmaxf(gm, red[j]);
    __syncthreads();

    float s = 0.0f;
#pragma unroll
    for (int i = 0; i < 8; i++) { r[i] = __expf(r[i] - gm); s += r[i]; }
#pragma unroll
    for (int o = 16; o > 0; o >>= 1)
        s += __shfl_xor_sync(0xFFFFFFFFu, s, o);
    if (lane == 0) red[wrp] = s;
    __syncthreads();
    float gs = red[0];
#pragma unroll
    for (int j = 1; j < 8; j++) gs += red[j];
    float inv = 1.0f / gs;

#pragma unroll
    for (int i = 0; i < 8; i++)
        Ph[row * SEQ + tid + i * 256] = __float2half(r[i] * inv);
}

// ------------------------------------------------------------------
// mma.sync fp16 split-emulated GEMM: C[M,N] = A[M,K] @ B[N,K]^T (NT)
// 256 threads, 8 warps 4x2, warp tile 32x64, BK=64, 3 stages.
// Compile-time MODE/EPI (smaller signature + folded branches):
// MODE 0: 3-pass A{hi,lo,hi} B{hi,hi,lo} | 3: 1-pass hi only
// EPI: 0 fp32 raw | 1 bias fp32 | 2 bias+split hi/lo | 3 bias+sigmoid fp16
//      4 bias fp16 | 5 gate(fp16)*acc -> fp16
// ------------------------------------------------------------------
#define STAGES 3
#define STAGE_BYTES 32768
#define GEMM_SMEM (STAGES * STAGE_BYTES)

template <int MODE, int EPI>
__global__ __launch_bounds__(256, 2)
void gemm3(const fp16* __restrict__ Ah, const fp16* __restrict__ Al,
           const fp16* __restrict__ Bh, const fp16* __restrict__ Bl,
           long long sAb, long long sBb, int K,
           float* __restrict__ Cf, fp16* __restrict__ Coh, fp16* __restrict__ Col,
           int ldc, long long sCb,
           const float* __restrict__ bias, const fp16* __restrict__ gateh,
           long long sGb)
{
    extern __shared__ char dsm[];
    const uint32_t sbase = smem_u32(dsm);

    const int tid  = threadIdx.x;
    const int wid  = tid >> 5;
    const int lane = tid & 31;
    const int wm = wid >> 1;          // 0..3
    const int wn = wid & 1;           // 0..1
    const int z  = blockIdx.z;
    Ah += (long long)z * sAb; Al += (long long)z * sAb;
    Bh += (long long)z * sBb; Bl += (long long)z * sBb;

    const int m0 = blockIdx.y * 128;
    const int n0 = blockIdx.x * 128;
    const int KC = K >> 6;
    constexpr int NPASS = (MODE == 0) ? 3 : ((MODE == 3) ? 1 : 2);
    const int NC = NPASS * KC;

    int rows[4], cols[4];
    uint32_t soff[4];
#pragma unroll
    for (int i = 0; i < 4; i++) {
        int idx = tid + i * 256;
        rows[i] = idx >> 3;
        cols[i] = idx & 7;
        soff[i] = (uint32_t)(rows[i] * 128 + ((cols[i] ^ (rows[i] & 7)) << 4));
    }

    auto load_chunk = [&](int c, int stage) {
        int phase = c / KC;
        int inner = c - phase * KC;
        const fp16* As = Ah;
        const fp16* Bs = Bh;
        if (MODE == 0) {
            if (phase == 1) As = Al;
            if (phase == 2) Bs = Bl;
        } else if (MODE == 1) {
            if (phase == 1) As = Al;
        } else if (MODE == 2) {
            if (phase == 1) Bs = Bl;
        }
        uint32_t aB = sbase + (uint32_t)stage * STAGE_BYTES;
        uint32_t bB = aB + 16384u;
#pragma unroll
        for (int i = 0; i < 4; i++)
            CP16(aB + soff[i], As + (size_t)(m0 + rows[i]) * K + inner * 64 + cols[i] * 8);
#pragma unroll
        for (int i = 0; i < 4; i++)
            CP16(bB + soff[i], Bs + (size_t)(n0 + rows[i]) * K + inner * 64 + cols[i] * 8);
    };

    load_chunk(0, 0); CP_COMMIT();
    load_chunk(1, 1); CP_COMMIT();

    float acc[2][8][4];
#pragma unroll
    for (int mt = 0; mt < 2; mt++)
#pragma unroll
        for (int nt = 0; nt < 8; nt++)
#pragma unroll
            for (int r = 0; r < 4; r++) acc[mt][nt][r] = 0.0f;

    const int aRowBase = wm * 32 + (lane & 15);
    const int bRowBase = wn * 64 + (lane & 15);
    const int khalf    = lane >> 4;

    for (int c = 0; c < NC; c++) {
        const int st = c % STAGES;
        CP_WAIT1();
        __syncthreads();
        if (c + 2 < NC) load_chunk(c + 2, (c + 2) % STAGES);
        CP_COMMIT();
        const uint32_t aB = sbase + (uint32_t)st * STAGE_BYTES;
        const uint32_t bB = aB + 16384u;
#pragma unroll
        for (int ks = 0; ks < 4; ks++) {
            const int ch = 2 * ks + khalf;
            uint32_t afr[2][4];
#pragma unroll
            for (int mt = 0; mt < 2; mt++) {
                int r = aRowBase + mt * 16;
                ldmx4(afr[mt], aB + (uint32_t)(r * 128 + ((ch ^ (r & 7)) << 4)));
            }
            uint32_t bfr[8][2];
#pragma unroll
            for (int nb = 0; nb < 4; nb++) {
                int r = bRowBase + nb * 16;
                uint32_t t4[4];
                ldmx4(t4, bB + (uint32_t)(r * 128 + ((ch ^ (r & 7)) << 4)));
                bfr[nb * 2][0]     = t4[0];
                bfr[nb * 2][1]     = t4[2];
                bfr[nb * 2 + 1][0] = t4[1];
                bfr[nb * 2 + 1][1] = t4[3];
            }
#pragma unroll
            for (int mt = 0; mt < 2; mt++)
#pragma unroll
                for (int nt = 0; nt < 8; nt++)
                    mma16816(acc[mt][nt], afr[mt], bfr[nt]);
        }
    }

    // ---------------- epilogue (compile-time EPI) ----------------
    const int erow0 = m0 + wm * 32 + (lane >> 2);
    const int ecol0 = n0 + wn * 64 + (lane & 3) * 2;

#pragma unroll
    for (int mt = 0; mt < 2; mt++) {
#pragma unroll
        for (int rr = 0; rr < 2; rr++) {
            const int row = erow0 + mt * 16 + rr * 8;
#pragma unroll
            for (int nt = 0; nt < 8; nt++) {
                const int col = ecol0 + nt * 8;
                float v0 = acc[mt][nt][2 * rr];
                float v1 = acc[mt][nt][2 * rr + 1];
                const size_t off = (size_t)z * sCb + (size_t)row * ldc + col;
                if (EPI == 0) {
                    *(float2*)(Cf + off) = make_float2(v0, v1);
                } else if (EPI == 1) {
                    v0 += bias[col]; v1 += bias[col + 1];
                    *(float2*)(Cf + off) = make_float2(v0, v1);
                } else if (EPI == 3 || EPI == 4) {
                    v0 += bias[col]; v1 += bias[col + 1];
                    if (EPI == 3) {
                        v0 = 1.0f / (1.0f + __expf(-v0));
                        v1 = 1.0f / (1.0f + __expf(-v1));
                    }
                    __half2 hh;
                    hh.x = __float2half(v0);
                    hh.y = __float2half(v1);
                    *(__half2*)(Coh + off) = hh;
                } else if (EPI == 5) {
                    __half2 gg = *(const __half2*)(gateh + (size_t)z * sGb +
                                                   (size_t)row * ldc + col);
                    __half2 hh;
                    hh.x = __float2half(v0 * __half2float(gg.x));
                    hh.y = __float2half(v1 * __half2float(gg.y));
                    *(__half2*)(Coh + off) = hh;
                } else { // EPI 2: bias + split hi/lo
                    v0 += bias[col]; v1 += bias[col + 1];
                    fp16 h0 = __float2half(v0), h1 = __float2half(v1);
                    __half2 hh, ll;
                    hh.x = h0; hh.y = h1;
                    ll.x = __float2half(v0 - __half2float(h0));
                    ll.y = __float2half(v1 - __half2float(h1));
                    *(__half2*)(Coh + off) = hh;
                    *(__half2*)(Col + off) = ll;
                }
            }
        }
    }
}

// ------------------------------------------------------------------
// launch
// ------------------------------------------------------------------
extern "C" void kernel_launch(void* const* d_in, const int* in_sizes, int n_in,
                              void* d_out, int out_size)
{
    const float* queries = (const float*)d_in[0];
    const float* keys    = (const float*)d_in[1];
    const float* values  = (const float*)d_in[2];
    const float* Wq = (const float*)d_in[3];
    const float* bq = (const float*)d_in[4];
    const float* Wk = (const float*)d_in[5];
    const float* bk = (const float*)d_in[6];
    const float* Wv = (const float*)d_in[7];
    const float* bv = (const float*)d_in[8];
    const float* Wg = (const float*)d_in[9];
    const float* bg = (const float*)d_in[10];
    const float* Wo = (const float*)d_in[11];
    const float* bo = (const float*)d_in[12];
    float* out = (float*)d_out;

    fp16 *iqh, *iql, *ikh, *ikl, *ivh, *wt;
    fp16 *qh, *ql, *kh, *kl, *v16, *vth, *gate16, *ph, *ch;
    float *sc;
    cudaGetSymbolAddress((void**)&iqh, g_iqh); cudaGetSymbolAddress((void**)&iql, g_iql);
    cudaGetSymbolAddress((void**)&ikh, g_ikh); cudaGetSymbolAddress((void**)&ikl, g_ikl);
    cudaGetSymbolAddress((void**)&ivh, g_ivh);
    cudaGetSymbolAddress((void**)&wt,  g_wt);
    cudaGetSymbolAddress((void**)&qh,  g_qh);  cudaGetSymbolAddress((void**)&ql,  g_ql);
    cudaGetSymbolAddress((void**)&kh,  g_kh);  cudaGetSymbolAddress((void**)&kl,  g_kl);
    cudaGetSymbolAddress((void**)&v16, g_v16);
    cudaGetSymbolAddress((void**)&vth, g_vth);
    cudaGetSymbolAddress((void**)&gate16, g_gate16);
    cudaGetSymbolAddress((void**)&sc,  g_sc);
    cudaGetSymbolAddress((void**)&ph,  g_ph);
    cudaGetSymbolAddress((void**)&ch,  g_ch);

    const size_t WSZ = (size_t)DDIM * DDIM;
    fp16* wth[5]; fp16* wtl[5];
    for (int w = 0; w < 5; w++) { wth[w] = wt + (2*w)*WSZ; wtl[w] = wt + (2*w+1)*WSZ; }

    cudaFuncSetAttribute(gemm3<0,2>, cudaFuncAttributeMaxDynamicSharedMemorySize, GEMM_SMEM);
    cudaFuncSetAttribute(gemm3<3,4>, cudaFuncAttributeMaxDynamicSharedMemorySize, GEMM_SMEM);
    cudaFuncSetAttribute(gemm3<3,3>, cudaFuncAttributeMaxDynamicSharedMemorySize, GEMM_SMEM);
    cudaFuncSetAttribute(gemm3<0,0>, cudaFuncAttributeMaxDynamicSharedMemorySize, GEMM_SMEM);
    cudaFuncSetAttribute(gemm3<3,5>, cudaFuncAttributeMaxDynamicSharedMemorySize, GEMM_SMEM);
    cudaFuncSetAttribute(gemm3<3,1>, cudaFuncAttributeMaxDynamicSharedMemorySize, GEMM_SMEM);

    const size_t nElem = (size_t)MTOT * DDIM;
    const int splitBlocks = (int)(nElem / 1024);
    dim3 tb(32, 8);
    dim3 gp(DDIM / 128, MTOT / 128, 1);

    // prep (R11 structure)
    split_f32<<<splitBlocks, 256>>>(queries, iqh, iql, nElem);
    split_f32<<<splitBlocks, 256>>>(keys,    ikh, ikl, nElem);
    conv_f16<<<splitBlocks, 256>>>(values,  ivh, nElem);
    transpose_split<<<dim3(32, 32), tb>>>(Wq, wth[0], wtl[0], DDIM, DDIM);
    transpose_split<<<dim3(32, 32), tb>>>(Wk, wth[1], wtl[1], DDIM, DDIM);
    // q proj — 3-pass
    gemm3<0,2><<<gp, 256, GEMM_SMEM>>>(iqh, iql, wth[0], wtl[0], 0, 0, DDIM,
                                       nullptr, qh, ql, DDIM, 0, bq, nullptr, 0);
    transpose_split<<<dim3(32, 32), tb>>>(Wv, wth[2], wtl[2], DDIM, DDIM);
    transpose_split<<<dim3(32, 32), tb>>>(Wg, wth[3], wtl[3], DDIM, DDIM);
    transpose_split<<<dim3(32, 32), tb>>>(Wo, wth[4], wtl[4], DDIM, DDIM);
    // k proj — 3-pass
    gemm3<0,2><<<gp, 256, GEMM_SMEM>>>(ikh, ikl, wth[1], wtl[1], 0, 0, DDIM,
                                       nullptr, kh, kl, DDIM, 0, bk, nullptr, 0);
    // v proj — 1-pass, fp16 out
    gemm3<3,4><<<gp, 256, GEMM_SMEM>>>(ivh, ivh, wth[2], wth[2], 0, 0, DDIM,
                                       nullptr, v16, nullptr, DDIM, 0, bv, nullptr, 0);
    // gate proj — 1-pass, sigmoid -> fp16
    gemm3<3,3><<<gp, 256, GEMM_SMEM>>>(iqh, iqh, wth[3], wth[3], 0, 0, DDIM,
                                       nullptr, gate16, nullptr, DDIM, 0, bg, nullptr, 0);

    // scores = q @ k^T (per batch) — 3-pass
    gemm3<0,0><<<dim3(SEQ / 128, SEQ / 128, BB), 256, GEMM_SMEM>>>(
        qh, ql, kh, kl, (long long)SEQ * DDIM, (long long)SEQ * DDIM, DDIM,
        sc, nullptr, nullptr, SEQ, (long long)SEQ * SEQ, nullptr, nullptr, 0);

    // softmax -> fp16 P
    softmax_p<<<MTOT, 256>>>(sc, ph);

    // transpose v per batch: fp16 [S,D] -> [D,S]
    transpose_h16<<<dim3(DDIM / 32, SEQ / 32, BB), tb>>>(
        v16, vth, SEQ, DDIM, (long long)SEQ * DDIM, (long long)SEQ * DDIM);

    // context = (P @ v) * gate -> fp16; 1-pass
    gemm3<3,5><<<dim3(DDIM / 128, SEQ / 128, BB), 256, GEMM_SMEM>>>(
        ph, ph, vth, vth, (long long)SEQ * SEQ, (long long)DDIM * SEQ, SEQ,
        nullptr, ch, nullptr, DDIM, (long long)SEQ * DDIM,
        nullptr, gate16, (long long)SEQ * DDIM);

    // out = ctx @ Wo + bo — 1-pass
    gemm3<3,1><<<gp, 256, GEMM_SMEM>>>(ch, ch, wth[4], wth[4], 0, 0, DDIM,
                                       out, nullptr, nullptr, DDIM, 0, bo, nullptr, 0);
}

// round 15
// speedup vs baseline: 1.0897x; 1.0079x over previous
#include <cuda_runtime.h>
#include <cuda_fp16.h>
#include <stdint.h>
#include <math.h>

typedef __half fp16;

#define BB 8
#define SEQ 2048
#define DDIM 1024
#define MTOT (BB * SEQ)   // 16384
#define NN ((size_t)MTOT * DDIM)

// ------------------------------------------------------------------
// PTX helpers (sm_80+ features only)
// ------------------------------------------------------------------
__device__ __forceinline__ uint32_t smem_u32(const void* p) {
    uint32_t a;
    asm("{ .reg .u64 t; cvta.to.shared.u64 t, %1; cvt.u32.u64 %0, t; }"
        : "=r"(a) : "l"(p));
    return a;
}
#define CP16(dst, src) \
    asm volatile("cp.async.cg.shared.global [%0], [%1], 16;" :: "r"(dst), "l"(src))
#define CP_COMMIT() asm volatile("cp.async.commit_group;" ::: "memory")
#define CP_WAIT1()  asm volatile("cp.async.wait_group 1;" ::: "memory")

__device__ __forceinline__ void ldmx4(uint32_t* r, uint32_t addr) {
    asm volatile("ldmatrix.sync.aligned.m8n8.x4.shared.b16 {%0,%1,%2,%3}, [%4];"
        : "=r"(r[0]), "=r"(r[1]), "=r"(r[2]), "=r"(r[3]) : "r"(addr));
}
__device__ __forceinline__ void mma16816(float* c, const uint32_t* a, const uint32_t* b) {
    asm("mma.sync.aligned.m16n8k16.row.col.f32.f16.f16.f32 "
        "{%0,%1,%2,%3}, {%4,%5,%6,%7}, {%8,%9}, {%0,%1,%2,%3};"
        : "+f"(c[0]), "+f"(c[1]), "+f"(c[2]), "+f"(c[3])
        : "r"(a[0]), "r"(a[1]), "r"(a[2]), "r"(a[3]), "r"(b[0]), "r"(b[1]));
}

// ------------------------------------------------------------------
// Scratch. Paired arrays guarantee equal z-strides for merged launches.
// ------------------------------------------------------------------
__device__ fp16 g_iqk_h[2][NN];   // input hi: 0=queries, 1=keys
__device__ fp16 g_iqk_l[2][NN];   // input lo
__device__ fp16 g_ivh[NN];
__device__ fp16 g_wt[5][2][(size_t)DDIM * DDIM];
__device__ fp16 g_qk_h[2][NN];    // proj out hi: 0=q, 1=k
__device__ fp16 g_qk_l[2][NN];
__device__ fp16 g_vg[2][NN];      // 0=v16, 1=gate16
__device__ fp16 g_vth[(size_t)BB * DDIM * SEQ];
__device__ float g_sc[(size_t)BB * SEQ * SEQ];
__device__ fp16 g_ph[(size_t)BB * SEQ * SEQ];
__device__ fp16 g_ch[NN];

// ------------------------------------------------------------------
// Elementwise split: fp32 -> hi(fp16), lo(fp16)
// ------------------------------------------------------------------
__global__ __launch_bounds__(256)
void split_f32(const float* __restrict__ x, fp16* __restrict__ h,
               fp16* __restrict__ l, size_t n)
{
    size_t i = ((size_t)blockIdx.x * 256 + threadIdx.x) * 4;
    if (i >= n) return;
    float4 v = *(const float4*)(x + i);
    fp16 h0 = __float2half(v.x), h1 = __float2half(v.y);
    fp16 h2 = __float2half(v.z), h3 = __float2half(v.w);
    __half2 hh0, hh1, ll0, ll1;
    hh0.x = h0; hh0.y = h1; hh1.x = h2; hh1.y = h3;
    ll0.x = __float2half(v.x - __half2float(h0));
    ll0.y = __float2half(v.y - __half2float(h1));
    ll1.x = __float2half(v.z - __half2float(h2));
    ll1.y = __float2half(v.w - __half2float(h3));
    *(__half2*)(h + i)     = hh0;
    *(__half2*)(h + i + 2) = hh1;
    *(__half2*)(l + i)     = ll0;
    *(__half2*)(l + i + 2) = ll1;
}

// ------------------------------------------------------------------
// Elementwise convert: fp32 -> fp16 (hi only)
// ------------------------------------------------------------------
__global__ __launch_bounds__(256)
void conv_f16(const float* __restrict__ x, fp16* __restrict__ h, size_t n)
{
    size_t i = ((size_t)blockIdx.x * 256 + threadIdx.x) * 4;
    if (i >= n) return;
    float4 v = *(const float4*)(x + i);
    __half2 a, b;
    a.x = __float2half(v.x); a.y = __float2half(v.y);
    b.x = __float2half(v.z); b.y = __float2half(v.w);
    *(__half2*)(h + i)     = a;
    *(__half2*)(h + i + 2) = b;
}

// ------------------------------------------------------------------
// Transpose + split: src [R,C] fp32 -> dst [C,R] hi/lo fp16 (weights)
// ------------------------------------------------------------------
__global__ __launch_bounds__(256)
void transpose_split(const float* __restrict__ src, fp16* __restrict__ dh,
                     fp16* __restrict__ dl, int R, int C)
{
    __shared__ float t[32][33];
    int r0 = blockIdx.y * 32, c0 = blockIdx.x * 32;
#pragma unroll
    for (int i = 0; i < 32; i += 8)
        t[threadIdx.y + i][threadIdx.x] =
            src[(size_t)(r0 + threadIdx.y + i) * C + c0 + threadIdx.x];
    __syncthreads();
#pragma unroll
    for (int i = 0; i < 32; i += 8) {
        int cc = c0 + threadIdx.y + i;
        int rr = r0 + threadIdx.x;
        float v = t[threadIdx.x][threadIdx.y + i];
        fp16 h = __float2half(v);
        dh[(size_t)cc * R + rr] = h;
        dl[(size_t)cc * R + rr] = __float2half(v - __half2float(h));
    }
}

// ------------------------------------------------------------------
// Transpose fp16 -> fp16: src [R,C] -> dst [C,R], batched
// ------------------------------------------------------------------
__global__ __launch_bounds__(256)
void transpose_h16(const fp16* __restrict__ src, fp16* __restrict__ dh,
                   int R, int C, long long sb, long long db)
{
    __shared__ fp16 t[32][34];
    src += (long long)blockIdx.z * sb;
    dh  += (long long)blockIdx.z * db;
    int r0 = blockIdx.y * 32, c0 = blockIdx.x * 32;
#pragma unroll
    for (int i = 0; i < 32; i += 8)
        t[threadIdx.y + i][threadIdx.x] =
            src[(size_t)(r0 + threadIdx.y + i) * C + c0 + threadIdx.x];
    __syncthreads();
#pragma unroll
    for (int i = 0; i < 32; i += 8) {
        int cc = c0 + threadIdx.y + i;
        int rr = r0 + threadIdx.x;
        dh[(size_t)cc * R + rr] = t[threadIdx.x][threadIdx.y + i];
    }
}

// ------------------------------------------------------------------
// Register-resident row softmax: one read + one fp16 write.
// ------------------------------------------------------------------
__global__ __launch_bounds__(256)
void softmax_p(const float* __restrict__ Sc, fp16* __restrict__ Ph)
{
    __shared__ float red[8];
    const size_t row = blockIdx.x;
    const int tid  = threadIdx.x;
    const int lane = tid & 31;
    const int wrp  = tid >> 5;
    const float* p = Sc + row * SEQ;

    float r[8];
#pragma unroll
    for (int i = 0; i < 8; i++) r[i] = p[tid + i * 256];

    float m = r[0];
#pragma unroll
    for (int i = 1; i < 8; i++) m = fmaxf(m, r[i]);
#pragma unroll
    for (int o = 16; o > 0; o >>= 1)
        m = fmaxf(m, __shfl_xor_sync(0xFFFFFFFFu, m, o));
    if (lane == 0) red[wrp] = m;
    __syncthreads();
    float gm = red[0];
#pragma unroll
    for (int j = 1; j < 8; j++) gm = fmaxf(gm, red[j]);
    __syncthreads();

    float s = 0.0f;
#pragma unroll
    for (int i = 0; i < 8; i++) { r[i] = __expf(r[i] - gm); s += r[i]; }
#pragma unroll
    for (int o = 16; o > 0; o >>= 1)
        s += __shfl_xor_sync(0xFFFFFFFFu, s, o);
    if (lane == 0) red[wrp] = s;
    __syncthreads();
    float gs = red[0];
#pragma unroll
    for (int j = 1; j < 8; j++) gs += red[j];
    float inv = 1.0f / gs;

#pragma unroll
    for (int i = 0; i < 8; i++)
        Ph[row * SEQ + tid + i * 256] = __float2half(r[i] * inv);
}

// ------------------------------------------------------------------
// mma.sync fp16 split-emulated GEMM: C[M,N] = A[M,K] @ B[N,K]^T (NT)
// 256 threads, 8 warps 4x2, warp tile 32x64, BK=64, 3 stages.
// MODE 0: 3-pass A{hi,lo,hi} B{hi,hi,lo} | 3: 1-pass hi only
// EPI: 0 fp32 raw | 1 bias fp32 | 2 bias+split hi/lo | 3 bias+sigmoid fp16
//      4 bias fp16 | 5 gate(fp16)*acc -> fp16
//      6 bias fp16, sigmoid iff blockIdx.z==1 (merged v+gate)
// sGb: gate batch stride (EPI5) or bias z-stride (other EPIs; 0 if unused).
// ------------------------------------------------------------------
#define STAGES 3
#define STAGE_BYTES 32768
#define GEMM_SMEM (STAGES * STAGE_BYTES)

template <int MODE, int EPI>
__global__ __launch_bounds__(256, 2)
void gemm3(const fp16* __restrict__ Ah, const fp16* __restrict__ Al,
           const fp16* __restrict__ Bh, const fp16* __restrict__ Bl,
           long long sAb, long long sBb, int K,
           float* __restrict__ Cf, fp16* __restrict__ Coh, fp16* __restrict__ Col,
           int ldc, long long sCb,
           const float* __restrict__ bias, const fp16* __restrict__ gateh,
           long long sGb)
{
    extern __shared__ char dsm[];
    const uint32_t sbase = smem_u32(dsm);

    const int tid  = threadIdx.x;
    const int wid  = tid >> 5;
    const int lane = tid & 31;
    const int wm = wid >> 1;          // 0..3
    const int wn = wid & 1;           // 0..1
    const int z  = blockIdx.z;
    Ah += (long long)z * sAb; Al += (long long)z * sAb;
    Bh += (long long)z * sBb; Bl += (long long)z * sBb;

    const int m0 = blockIdx.y * 128;
    const int n0 = blockIdx.x * 128;
    const int KC = K >> 6;
    constexpr int NPASS = (MODE == 0) ? 3 : ((MODE == 3) ? 1 : 2);
    const int NC = NPASS * KC;

    int rows[4], cols[4];
    uint32_t soff[4];
#pragma unroll
    for (int i = 0; i < 4; i++) {
        int idx = tid + i * 256;
        rows[i] = idx >> 3;
        cols[i] = idx & 7;
        soff[i] = (uint32_t)(rows[i] * 128 + ((cols[i] ^ (rows[i] & 7)) << 4));
    }

    auto load_chunk = [&](int c, int stage) {
        int phase = c / KC;
        int inner = c - phase * KC;
        const fp16* As = Ah;
        const fp16* Bs = Bh;
        if (MODE == 0) {
            if (phase == 1) As = Al;
            if (phase == 2) Bs = Bl;
        } else if (MODE == 1) {
            if (phase == 1) As = Al;
        } else if (MODE == 2) {
            if (phase == 1) Bs = Bl;
        }
        uint32_t aB = sbase + (uint32_t)stage * STAGE_BYTES;
        uint32_t bB = aB + 16384u;
#pragma unroll
        for (int i = 0; i < 4; i++)
            CP16(aB + soff[i], As + (size_t)(m0 + rows[i]) * K + inner * 64 + cols[i] * 8);
#pragma unroll
        for (int i = 0; i < 4; i++)
            CP16(bB + soff[i], Bs + (size_t)(n0 + rows[i]) * K + inner * 64 + cols[i] * 8);
    };

    load_chunk(0, 0); CP_COMMIT();
    load_chunk(1, 1); CP_COMMIT();

    float acc[2][8][4];
#pragma unroll
    for (int mt = 0; mt < 2; mt++)
#pragma unroll
        for (int nt = 0; nt < 8; nt++)
#pragma unroll
            for (int r = 0; r < 4; r++) acc[mt][nt][r] = 0.0f;

    const int aRowBase = wm * 32 + (lane & 15);
    const int bRowBase = wn * 64 + (lane & 15);
    const int khalf    = lane >> 4;

    for (int c = 0; c < NC; c++) {
        const int st = c % STAGES;
        CP_WAIT1();
        __syncthreads();
        if (c + 2 < NC) load_chunk(c + 2, (c + 2) % STAGES);
        CP_COMMIT();
        const uint32_t aB = sbase + (uint32_t)st * STAGE_BYTES;
        const uint32_t bB = aB + 16384u;
#pragma unroll
        for (int ks = 0; ks < 4; ks++) {
            const int ch = 2 * ks + khalf;
            uint32_t afr[2][4];
#pragma unroll
            for (int mt = 0; mt < 2; mt++) {
                int r = aRowBase + mt * 16;
                ldmx4(afr[mt], aB + (uint32_t)(r * 128 + ((ch ^ (r & 7)) << 4)));
            }
            uint32_t bfr[8][2];
#pragma unroll
            for (int nb = 0; nb < 4; nb++) {
                int r = bRowBase + nb * 16;
                uint32_t t4[4];
                ldmx4(t4, bB + (uint32_t)(r * 128 + ((ch ^ (r & 7)) << 4)));
                bfr[nb * 2][0]     = t4[0];
                bfr[nb * 2][1]     = t4[2];
                bfr[nb * 2 + 1][0] = t4[1];
                bfr[nb * 2 + 1][1] = t4[3];
            }
#pragma unroll
            for (int mt = 0; mt < 2; mt++)
#pragma unroll
                for (int nt = 0; nt < 8; nt++)
                    mma16816(acc[mt][nt], afr[mt], bfr[nt]);
        }
    }

    // ---------------- epilogue (compile-time EPI) ----------------
    // bias z-offset (sGb doubles as bias stride for bias-using EPIs)
    const float* biasz = (EPI == 5 || EPI == 0) ? bias
                       : bias + (long long)z * sGb;
    const int erow0 = m0 + wm * 32 + (lane >> 2);
    const int ecol0 = n0 + wn * 64 + (lane & 3) * 2;

#pragma unroll
    for (int mt = 0; mt < 2; mt++) {
#pragma unroll
        for (int rr = 0; rr < 2; rr++) {
            const int row = erow0 + mt * 16 + rr * 8;
#pragma unroll
            for (int nt = 0; nt < 8; nt++) {
                const int col = ecol0 + nt * 8;
                float v0 = acc[mt][nt][2 * rr];
                float v1 = acc[mt][nt][2 * rr + 1];
                const size_t off = (size_t)z * sCb + (size_t)row * ldc + col;
                if (EPI == 0) {
                    *(float2*)(Cf + off) = make_float2(v0, v1);
                } else if (EPI == 1) {
                    v0 += biasz[col]; v1 += biasz[col + 1];
                    *(float2*)(Cf + off) = make_float2(v0, v1);
                } else if (EPI == 3 || EPI == 4) {
                    v0 += biasz[col]; v1 += biasz[col + 1];
                    if (EPI == 3) {
                        v0 = 1.0f / (1.0f + __expf(-v0));
                        v1 = 1.0f / (1.0f + __expf(-v1));
                    }
                    __half2 hh;
                    hh.x = __float2half(v0);
                    hh.y = __float2half(v1);
                    *(__half2*)(Coh + off) = hh;
                } else if (EPI == 5) {
                    __half2 gg = *(const __half2*)(gateh + (size_t)z * sGb +
                                                   (size_t)row * ldc + col);
                    __half2 hh;
                    hh.x = __float2half(v0 * __half2float(gg.x));
                    hh.y = __float2half(v1 * __half2float(gg.y));
                    *(__half2*)(Coh + off) = hh;
                } else if (EPI == 6) {
                    v0 += biasz[col]; v1 += biasz[col + 1];
                    if (z == 1) {   // gate slot: sigmoid
                        v0 = 1.0f / (1.0f + __expf(-v0));
                        v1 = 1.0f / (1.0f + __expf(-v1));
                    }
                    __half2 hh;
                    hh.x = __float2half(v0);
                    hh.y = __float2half(v1);
                    *(__half2*)(Coh + off) = hh;
                } else { // EPI 2: bias + split hi/lo
                    v0 += biasz[col]; v1 += biasz[col + 1];
                    fp16 h0 = __float2half(v0), h1 = __float2half(v1);
                    __half2 hh, ll;
                    hh.x = h0; hh.y = h1;
                    ll.x = __float2half(v0 - __half2float(h0));
                    ll.y = __float2half(v1 - __half2float(h1));
                    *(__half2*)(Coh + off) = hh;
                    *(__half2*)(Col + off) = ll;
                }
            }
        }
    }
}

// ------------------------------------------------------------------
// launch
// ------------------------------------------------------------------
extern "C" void kernel_launch(void* const* d_in, const int* in_sizes, int n_in,
                              void* d_out, int out_size)
{
    const float* queries = (const float*)d_in[0];
    const float* keys    = (const float*)d_in[1];
    const float* values  = (const float*)d_in[2];
    const float* Wq = (const float*)d_in[3];
    const float* bq = (const float*)d_in[4];
    const float* Wk = (const float*)d_in[5];
    const float* bk = (const float*)d_in[6];
    const float* Wv = (const float*)d_in[7];
    const float* bv = (const float*)d_in[8];
    const float* Wg = (const float*)d_in[9];
    const float* bg = (const float*)d_in[10];
    const float* Wo = (const float*)d_in[11];
    const float* bo = (const float*)d_in[12];
    float* out = (float*)d_out;

    fp16 *iqkh, *iqkl, *ivh, *wt, *qkh, *qkl, *vg, *vth, *ph, *ch;
    float *sc;
    cudaGetSymbolAddress((void**)&iqkh, g_iqk_h);
    cudaGetSymbolAddress((void**)&iqkl, g_iqk_l);
    cudaGetSymbolAddress((void**)&ivh,  g_ivh);
    cudaGetSymbolAddress((void**)&wt,   g_wt);
    cudaGetSymbolAddress((void**)&qkh,  g_qk_h);
    cudaGetSymbolAddress((void**)&qkl,  g_qk_l);
    cudaGetSymbolAddress((void**)&vg,   g_vg);
    cudaGetSymbolAddress((void**)&vth,  g_vth);
    cudaGetSymbolAddress((void**)&sc,   g_sc);
    cudaGetSymbolAddress((void**)&ph,   g_ph);
    cudaGetSymbolAddress((void**)&ch,   g_ch);

    const size_t WSZ = (size_t)DDIM * DDIM;
    fp16* wth[5]; fp16* wtl[5];
    for (int w = 0; w < 5; w++) { wth[w] = wt + (2*w)*WSZ; wtl[w] = wt + (2*w+1)*WSZ; }

    cudaFuncSetAttribute(gemm3<0,2>, cudaFuncAttributeMaxDynamicSharedMemorySize, GEMM_SMEM);
    cudaFuncSetAttribute(gemm3<3,6>, cudaFuncAttributeMaxDynamicSharedMemorySize, GEMM_SMEM);
    cudaFuncSetAttribute(gemm3<0,0>, cudaFuncAttributeMaxDynamicSharedMemorySize, GEMM_SMEM);
    cudaFuncSetAttribute(gemm3<3,5>, cudaFuncAttributeMaxDynamicSharedMemorySize, GEMM_SMEM);
    cudaFuncSetAttribute(gemm3<3,1>, cudaFuncAttributeMaxDynamicSharedMemorySize, GEMM_SMEM);

    const int splitBlocks = (int)(NN / 1024);
    dim3 tb(32, 8);
    dim3 gp(DDIM / 128, MTOT / 128, 1);

    // prep
    split_f32<<<splitBlocks, 256>>>(queries, iqkh,      iqkl,      NN);
    split_f32<<<splitBlocks, 256>>>(keys,    iqkh + NN, iqkl + NN, NN);
    conv_f16<<<splitBlocks, 256>>>(values,  ivh, NN);
    transpose_split<<<dim3(32, 32), tb>>>(Wq, wth[0], wtl[0], DDIM, DDIM);
    transpose_split<<<dim3(32, 32), tb>>>(Wk, wth[1], wtl[1], DDIM, DDIM);
    transpose_split<<<dim3(32, 32), tb>>>(Wv, wth[2], wtl[2], DDIM, DDIM);
    transpose_split<<<dim3(32, 32), tb>>>(Wg, wth[3], wtl[3], DDIM, DDIM);
    transpose_split<<<dim3(32, 32), tb>>>(Wo, wth[4], wtl[4], DDIM, DDIM);

    // q+k projections — 3-pass, merged: z strides select q(0)/k(1)
    gemm3<0,2><<<dim3(DDIM / 128, MTOT / 128, 2), 256, GEMM_SMEM>>>(
        iqkh, iqkl, wth[0], wtl[0],
        (long long)NN, (long long)(2 * WSZ), DDIM,
        nullptr, qkh, qkl, DDIM, (long long)NN,
        bq, nullptr, (long long)(bk - bq));

    // v+gate projections — 1-pass, merged: z=0 v (plain), z=1 gate (sigmoid)
    gemm3<3,6><<<dim3(DDIM / 128, MTOT / 128, 2), 256, GEMM_SMEM>>>(
        ivh, ivh, wth[2], wth[2],
        (long long)(iqkh - ivh), (long long)(2 * WSZ), DDIM,
        nullptr, vg, nullptr, DDIM, (long long)NN,
        bv, nullptr, (long long)(bg - bv));

    // scores = q @ k^T (per batch) — 3-pass
    gemm3<0,0><<<dim3(SEQ / 128, SEQ / 128, BB), 256, GEMM_SMEM>>>(
        qkh, qkl, qkh + NN, qkl + NN,
        (long long)SEQ * DDIM, (long long)SEQ * DDIM, DDIM,
        sc, nullptr, nullptr, SEQ, (long long)SEQ * SEQ, nullptr, nullptr, 0);

    // softmax -> fp16 P
    softmax_p<<<MTOT, 256>>>(sc, ph);

    // transpose v per batch: fp16 [S,D] -> [D,S]
    transpose_h16<<<dim3(DDIM / 32, SEQ / 32, BB), tb>>>(
        vg, vth, SEQ, DDIM, (long long)SEQ * DDIM, (long long)SEQ * DDIM);

    // context = (P @ v) * gate -> fp16; 1-pass
    gemm3<3,5><<<dim3(DDIM / 128, SEQ / 128, BB), 256, GEMM_SMEM>>>(
        ph, ph, vth, vth, (long long)SEQ * SEQ, (long long)DDIM * SEQ, SEQ,
        nullptr, ch, nullptr, DDIM, (long long)SEQ * DDIM,
        nullptr, vg + NN, (long long)SEQ * DDIM);

    // out = ctx @ Wo + bo — 1-pass
    gemm3<3,1><<<gp, 256, GEMM_SMEM>>>(ch, ch, wth[4], wth[4], 0, 0, DDIM,
                                       out, nullptr, nullptr, DDIM, 0, bo, nullptr, 0);
}

// round 16
// speedup vs baseline: 1.0952x; 1.0051x over previous
#include <cuda_runtime.h>
#include <cuda_fp16.h>
#include <stdint.h>
#include <math.h>

typedef __half fp16;

#define BB 8
#define SEQ 2048
#define DDIM 1024
#define MTOT (BB * SEQ)   // 16384
#define NN ((size_t)MTOT * DDIM)

// ------------------------------------------------------------------
// PTX helpers (sm_80+ features only)
// ------------------------------------------------------------------
__device__ __forceinline__ uint32_t smem_u32(const void* p) {
    uint32_t a;
    asm("{ .reg .u64 t; cvta.to.shared.u64 t, %1; cvt.u32.u64 %0, t; }"
        : "=r"(a) : "l"(p));
    return a;
}
#define CP16(dst, src) \
    asm volatile("cp.async.cg.shared.global [%0], [%1], 16;" :: "r"(dst), "l"(src))
#define CP_COMMIT() asm volatile("cp.async.commit_group;" ::: "memory")
#define CP_WAIT1()  asm volatile("cp.async.wait_group 1;" ::: "memory")

__device__ __forceinline__ void ldmx4(uint32_t* r, uint32_t addr) {
    asm volatile("ldmatrix.sync.aligned.m8n8.x4.shared.b16 {%0,%1,%2,%3}, [%4];"
        : "=r"(r[0]), "=r"(r[1]), "=r"(r[2]), "=r"(r[3]) : "r"(addr));
}
__device__ __forceinline__ void mma16816(float* c, const uint32_t* a, const uint32_t* b) {
    asm("mma.sync.aligned.m16n8k16.row.col.f32.f16.f16.f32 "
        "{%0,%1,%2,%3}, {%4,%5,%6,%7}, {%8,%9}, {%0,%1,%2,%3};"
        : "+f"(c[0]), "+f"(c[1]), "+f"(c[2]), "+f"(c[3])
        : "r"(a[0]), "r"(a[1]), "r"(a[2]), "r"(a[3]), "r"(b[0]), "r"(b[1]));
}

// ------------------------------------------------------------------
// Scratch. Paired arrays guarantee equal z-strides for merged launches.
// ------------------------------------------------------------------
__device__ fp16 g_iqk_h[2][NN];   // input hi: 0=queries, 1=keys
__device__ fp16 g_iqk_l[2][NN];   // input lo
__device__ fp16 g_ivh[NN];
__device__ fp16 g_wt[5][2][(size_t)DDIM * DDIM];
__device__ fp16 g_qk_h[2][NN];    // proj out hi: 0=q, 1=k
__device__ fp16 g_qk_l[2][NN];
__device__ fp16 g_vg[2][NN];      // 0=v16, 1=gate16
__device__ fp16 g_vth[(size_t)BB * DDIM * SEQ];
__device__ float g_sc[(size_t)BB * SEQ * SEQ];
__device__ fp16 g_ph[(size_t)BB * SEQ * SEQ];
__device__ fp16 g_ch[NN];

// ------------------------------------------------------------------
// Merged input prep: z=0 split queries, z=1 split keys, z=2 convert values
// ------------------------------------------------------------------
__global__ __launch_bounds__(256)
void prep_inputs(const float* __restrict__ q, const float* __restrict__ k,
                 const float* __restrict__ vv,
                 fp16* __restrict__ qkh, fp16* __restrict__ qkl,
                 fp16* __restrict__ vh)
{
    size_t i = ((size_t)blockIdx.x * 256 + threadIdx.x) * 4;
    const int z = blockIdx.z;
    if (z == 2) {
        float4 v = *(const float4*)(vv + i);
        __half2 a, b;
        a.x = __float2half(v.x); a.y = __float2half(v.y);
        b.x = __float2half(v.z); b.y = __float2half(v.w);
        *(__half2*)(vh + i)     = a;
        *(__half2*)(vh + i + 2) = b;
        return;
    }
    const float* src = (z == 0) ? q : k;
    fp16* h = qkh + (size_t)z * NN;
    fp16* l = qkl + (size_t)z * NN;
    float4 v = *(const float4*)(src + i);
    fp16 h0 = __float2half(v.x), h1 = __float2half(v.y);
    fp16 h2 = __float2half(v.z), h3 = __float2half(v.w);
    __half2 hh0, hh1, ll0, ll1;
    hh0.x = h0; hh0.y = h1; hh1.x = h2; hh1.y = h3;
    ll0.x = __float2half(v.x - __half2float(h0));
    ll0.y = __float2half(v.y - __half2float(h1));
    ll1.x = __float2half(v.z - __half2float(h2));
    ll1.y = __float2half(v.w - __half2float(h3));
    *(__half2*)(h + i)     = hh0;
    *(__half2*)(h + i + 2) = hh1;
    *(__half2*)(l + i)     = ll0;
    *(__half2*)(l + i + 2) = ll1;
}

// ------------------------------------------------------------------
// Merged weight transpose+split: z selects weight; lo written only z<2
// ------------------------------------------------------------------
__global__ __launch_bounds__(256)
void tweights(const float* __restrict__ W0, const float* __restrict__ W1,
              const float* __restrict__ W2, const float* __restrict__ W3,
              const float* __restrict__ W4, fp16* __restrict__ wtbase)
{
    __shared__ float t[32][33];
    const int z = blockIdx.z;
    const float* src = (z == 0) ? W0 : (z == 1) ? W1 : (z == 2) ? W2
                     : (z == 3) ? W3 : W4;
    fp16* dh = wtbase + (size_t)(2 * z)     * DDIM * DDIM;
    fp16* dl = wtbase + (size_t)(2 * z + 1) * DDIM * DDIM;
    const bool wantLo = (z < 2);
    int r0 = blockIdx.y * 32, c0 = blockIdx.x * 32;
#pragma unroll
    for (int i = 0; i < 32; i += 8)
        t[threadIdx.y + i][threadIdx.x] =
            src[(size_t)(r0 + threadIdx.y + i) * DDIM + c0 + threadIdx.x];
    __syncthreads();
#pragma unroll
    for (int i = 0; i < 32; i += 8) {
        int cc = c0 + threadIdx.y + i;
        int rr = r0 + threadIdx.x;
        float v = t[threadIdx.x][threadIdx.y + i];
        fp16 h = __float2half(v);
        dh[(size_t)cc * DDIM + rr] = h;
        if (wantLo)
            dl[(size_t)cc * DDIM + rr] = __float2half(v - __half2float(h));
    }
}

// ------------------------------------------------------------------
// Transpose fp16 -> fp16: src [R,C] -> dst [C,R], batched
// ------------------------------------------------------------------
__global__ __launch_bounds__(256)
void transpose_h16(const fp16* __restrict__ src, fp16* __restrict__ dh,
                   int R, int C, long long sb, long long db)
{
    __shared__ fp16 t[32][34];
    src += (long long)blockIdx.z * sb;
    dh  += (long long)blockIdx.z * db;
    int r0 = blockIdx.y * 32, c0 = blockIdx.x * 32;
#pragma unroll
    for (int i = 0; i < 32; i += 8)
        t[threadIdx.y + i][threadIdx.x] =
            src[(size_t)(r0 + threadIdx.y + i) * C + c0 + threadIdx.x];
    __syncthreads();
#pragma unroll
    for (int i = 0; i < 32; i += 8) {
        int cc = c0 + threadIdx.y + i;
        int rr = r0 + threadIdx.x;
        dh[(size_t)cc * R + rr] = t[threadIdx.x][threadIdx.y + i];
    }
}

// ------------------------------------------------------------------
// Register-resident row softmax: one read + one fp16 write.
// ------------------------------------------------------------------
__global__ __launch_bounds__(256)
void softmax_p(const float* __restrict__ Sc, fp16* __restrict__ Ph)
{
    __shared__ float red[8];
    const size_t row = blockIdx.x;
    const int tid  = threadIdx.x;
    const int lane = tid & 31;
    const int wrp  = tid >> 5;
    const float* p = Sc + row * SEQ;

    float r[8];
#pragma unroll
    for (int i = 0; i < 8; i++) r[i] = p[tid + i * 256];

    float m = r[0];
#pragma unroll
    for (int i = 1; i < 8; i++) m = fmaxf(m, r[i]);
#pragma unroll
    for (int o = 16; o > 0; o >>= 1)
        m = fmaxf(m, __shfl_xor_sync(0xFFFFFFFFu, m, o));
    if (lane == 0) red[wrp] = m;
    __syncthreads();
    float gm = red[0];
#pragma unroll
    for (int j = 1; j < 8; j++) gm = fmaxf(gm, red[j]);
    __syncthreads();

    float s = 0.0f;
#pragma unroll
    for (int i = 0; i < 8; i++) { r[i] = __expf(r[i] - gm); s += r[i]; }
#pragma unroll
    for (int o = 16; o > 0; o >>= 1)
        s += __shfl_xor_sync(0xFFFFFFFFu, s, o);
    if (lane == 0) red[wrp] = s;
    __syncthreads();
    float gs = red[0];
#pragma unroll
    for (int j = 1; j < 8; j++) gs += red[j];
    float inv = 1.0f / gs;

#pragma unroll
    for (int i = 0; i < 8; i++)
        Ph[row * SEQ + tid + i * 256] = __float2half(r[i] * inv);
}

// ------------------------------------------------------------------
// mma.sync fp16 split-emulated GEMM: C[M,N] = A[M,K] @ B[N,K]^T (NT)
// 256 threads, 8 warps 4x2, warp tile 32x64, BK=64, 3 stages.
// MODE 0: 3-pass A{hi,lo,hi} B{hi,hi,lo} | 3: 1-pass hi only
// EPI: 0 fp32 raw | 1 bias fp32 | 2 bias+split hi/lo | 3 bias+sigmoid fp16
//      4 bias fp16 | 5 gate(fp16)*acc -> fp16
//      6 bias fp16, sigmoid iff blockIdx.z==1 (merged v+gate)
// sGb: gate batch stride (EPI5) or bias z-stride (other EPIs; 0 if unused).
// ------------------------------------------------------------------
#define STAGES 3
#define STAGE_BYTES 32768
#define GEMM_SMEM (STAGES * STAGE_BYTES)

template <int MODE, int EPI>
__global__ __launch_bounds__(256, 2)
void gemm3(const fp16* __restrict__ Ah, const fp16* __restrict__ Al,
           const fp16* __restrict__ Bh, const fp16* __restrict__ Bl,
           long long sAb, long long sBb, int K,
           float* __restrict__ Cf, fp16* __restrict__ Coh, fp16* __restrict__ Col,
           int ldc, long long sCb,
           const float* __restrict__ bias, const fp16* __restrict__ gateh,
           long long sGb)
{
    extern __shared__ char dsm[];
    const uint32_t sbase = smem_u32(dsm);

    const int tid  = threadIdx.x;
    const int wid  = tid >> 5;
    const int lane = tid & 31;
    const int wm = wid >> 1;          // 0..3
    const int wn = wid & 1;           // 0..1
    const int z  = blockIdx.z;
    Ah += (long long)z * sAb; Al += (long long)z * sAb;
    Bh += (long long)z * sBb; Bl += (long long)z * sBb;

    const int m0 = blockIdx.y * 128;
    const int n0 = blockIdx.x * 128;
    const int KC = K >> 6;
    constexpr int NPASS = (MODE == 0) ? 3 : ((MODE == 3) ? 1 : 2);
    const int NC = NPASS * KC;

    int rows[4], cols[4];
    uint32_t soff[4];
#pragma unroll
    for (int i = 0; i < 4; i++) {
        int idx = tid + i * 256;
        rows[i] = idx >> 3;
        cols[i] = idx & 7;
        soff[i] = (uint32_t)(rows[i] * 128 + ((cols[i] ^ (rows[i] & 7)) << 4));
    }

    auto load_chunk = [&](int c, int stage) {
        int phase = c / KC;
        int inner = c - phase * KC;
        const fp16* As = Ah;
        const fp16* Bs = Bh;
        if (MODE == 0) {
            if (phase == 1) As = Al;
            if (phase == 2) Bs = Bl;
        } else if (MODE == 1) {
            if (phase == 1) As = Al;
        } else if (MODE == 2) {
            if (phase == 1) Bs = Bl;
        }
        uint32_t aB = sbase + (uint32_t)stage * STAGE_BYTES;
        uint32_t bB = aB + 16384u;
#pragma unroll
        for (int i = 0; i < 4; i++)
            CP16(aB + soff[i], As + (size_t)(m0 + rows[i]) * K + inner * 64 + cols[i] * 8);
#pragma unroll
        for (int i = 0; i < 4; i++)
            CP16(bB + soff[i], Bs + (size_t)(n0 + rows[i]) * K + inner * 64 + cols[i] * 8);
    };

    load_chunk(0, 0); CP_COMMIT();
    load_chunk(1, 1); CP_COMMIT();

    float acc[2][8][4];
#pragma unroll
    for (int mt = 0; mt < 2; mt++)
#pragma unroll
        for (int nt = 0; nt < 8; nt++)
#pragma unroll
            for (int r = 0; r < 4; r++) acc[mt][nt][r] = 0.0f;

    const int aRowBase = wm * 32 + (lane & 15);
    const int bRowBase = wn * 64 + (lane & 15);
    const int khalf    = lane >> 4;

    for (int c = 0; c < NC; c++) {
        const int st = c % STAGES;
        CP_WAIT1();
        __syncthreads();
        if (c + 2 < NC) load_chunk(c + 2, (c + 2) % STAGES);
        CP_COMMIT();
        const uint32_t aB = sbase + (uint32_t)st * STAGE_BYTES;
        const uint32_t bB = aB + 16384u;
#pragma unroll
        for (int ks = 0; ks < 4; ks++) {
            const int ch = 2 * ks + khalf;
            uint32_t afr[2][4];
#pragma unroll
            for (int mt = 0; mt < 2; mt++) {
                int r = aRowBase + mt * 16;
                ldmx4(afr[mt], aB + (uint32_t)(r * 128 + ((ch ^ (r & 7)) << 4)));
            }
            uint32_t bfr[8][2];
#pragma unroll
            for (int nb = 0; nb < 4; nb++) {
                int r = bRowBase + nb * 16;
                uint32_t t4[4];
                ldmx4(t4, bB + (uint32_t)(r * 128 + ((ch ^ (r & 7)) << 4)));
                bfr[nb * 2][0]     = t4[0];
                bfr[nb * 2][1]     = t4[2];
                bfr[nb * 2 + 1][0] = t4[1];
                bfr[nb * 2 + 1][1] = t4[3];
            }
#pragma unroll
            for (int mt = 0; mt < 2; mt++)
#pragma unroll
                for (int nt = 0; nt < 8; nt++)
                    mma16816(acc[mt][nt], afr[mt], bfr[nt]);
        }
    }

    // ---------------- epilogue (compile-time EPI) ----------------
    const float* biasz = (EPI == 5 || EPI == 0) ? bias
                       : bias + (long long)z * sGb;
    const int erow0 = m0 + wm * 32 + (lane >> 2);
    const int ecol0 = n0 + wn * 64 + (lane & 3) * 2;

#pragma unroll
    for (int mt = 0; mt < 2; mt++) {
#pragma unroll
        for (int rr = 0; rr < 2; rr++) {
            const int row = erow0 + mt * 16 + rr * 8;
#pragma unroll
            for (int nt = 0; nt < 8; nt++) {
                const int col = ecol0 + nt * 8;
                float v0 = acc[mt][nt][2 * rr];
                float v1 = acc[mt][nt][2 * rr + 1];
                const size_t off = (size_t)z * sCb + (size_t)row * ldc + col;
                if (EPI == 0) {
                    *(float2*)(Cf + off) = make_float2(v0, v1);
                } else if (EPI == 1) {
                    v0 += biasz[col]; v1 += biasz[col + 1];
                    *(float2*)(Cf + off) = make_float2(v0, v1);
                } else if (EPI == 3 || EPI == 4) {
                    v0 += biasz[col]; v1 += biasz[col + 1];
                    if (EPI == 3) {
                        v0 = 1.0f / (1.0f + __expf(-v0));
                        v1 = 1.0f / (1.0f + __expf(-v1));
                    }
                    __half2 hh;
                    hh.x = __float2half(v0);
                    hh.y = __float2half(v1);
                    *(__half2*)(Coh + off) = hh;
                } else if (EPI == 5) {
                    __half2 gg = *(const __half2*)(gateh + (size_t)z * sGb +
                                                   (size_t)row * ldc + col);
                    __half2 hh;
                    hh.x = __float2half(v0 * __half2float(gg.x));
                    hh.y = __float2half(v1 * __half2float(gg.y));
                    *(__half2*)(Coh + off) = hh;
                } else if (EPI == 6) {
                    v0 += biasz[col]; v1 += biasz[col + 1];
                    if (z == 1) {   // gate slot: sigmoid
                        v0 = 1.0f / (1.0f + __expf(-v0));
                        v1 = 1.0f / (1.0f + __expf(-v1));
                    }
                    __half2 hh;
                    hh.x = __float2half(v0);
                    hh.y = __float2half(v1);
                    *(__half2*)(Coh + off) = hh;
                } else { // EPI 2: bias + split hi/lo
                    v0 += biasz[col]; v1 += biasz[col + 1];
                    fp16 h0 = __float2half(v0), h1 = __float2half(v1);
                    __half2 hh, ll;
                    hh.x = h0; hh.y = h1;
                    ll.x = __float2half(v0 - __half2float(h0));
                    ll.y = __float2half(v1 - __half2float(h1));
                    *(__half2*)(Coh + off) = hh;
                    *(__half2*)(Col + off) = ll;
                }
            }
        }
    }
}

// ------------------------------------------------------------------
// launch
// ------------------------------------------------------------------
extern "C" void kernel_launch(void* const* d_in, const int* in_sizes, int n_in,
                              void* d_out, int out_size)
{
    const float* queries = (const float*)d_in[0];
    const float* keys    = (const float*)d_in[1];
    const float* values  = (const float*)d_in[2];
    const float* Wq = (const float*)d_in[3];
    const float* bq = (const float*)d_in[4];
    const float* Wk = (const float*)d_in[5];
    const float* bk = (const float*)d_in[6];
    const float* Wv = (const float*)d_in[7];
    const float* bv = (const float*)d_in[8];
    const float* Wg = (const float*)d_in[9];
    const float* bg = (const float*)d_in[10];
    const float* Wo = (const float*)d_in[11];
    const float* bo = (const float*)d_in[12];
    float* out = (float*)d_out;

    fp16 *iqkh, *iqkl, *ivh, *wt, *qkh, *qkl, *vg, *vth, *ph, *ch;
    float *sc;
    cudaGetSymbolAddress((void**)&iqkh, g_iqk_h);
    cudaGetSymbolAddress((void**)&iqkl, g_iqk_l);
    cudaGetSymbolAddress((void**)&ivh,  g_ivh);
    cudaGetSymbolAddress((void**)&wt,   g_wt);
    cudaGetSymbolAddress((void**)&qkh,  g_qk_h);
    cudaGetSymbolAddress((void**)&qkl,  g_qk_l);
    cudaGetSymbolAddress((void**)&vg,   g_vg);
    cudaGetSymbolAddress((void**)&vth,  g_vth);
    cudaGetSymbolAddress((void**)&sc,   g_sc);
    cudaGetSymbolAddress((void**)&ph,   g_ph);
    cudaGetSymbolAddress((void**)&ch,   g_ch);

    const size_t WSZ = (size_t)DDIM * DDIM;
    fp16* wth[5]; fp16* wtl[5];
    for (int w = 0; w < 5; w++) { wth[w] = wt + (2*w)*WSZ; wtl[w] = wt + (2*w+1)*WSZ; }

    cudaFuncSetAttribute(gemm3<0,2>, cudaFuncAttributeMaxDynamicSharedMemorySize, GEMM_SMEM);
    cudaFuncSetAttribute(gemm3<3,6>, cudaFuncAttributeMaxDynamicSharedMemorySize, GEMM_SMEM);
    cudaFuncSetAttribute(gemm3<0,0>, cudaFuncAttributeMaxDynamicSharedMemorySize, GEMM_SMEM);
    cudaFuncSetAttribute(gemm3<3,5>, cudaFuncAttributeMaxDynamicSharedMemorySize, GEMM_SMEM);
    cudaFuncSetAttribute(gemm3<3,1>, cudaFuncAttributeMaxDynamicSharedMemorySize, GEMM_SMEM);

    const int splitBlocks = (int)(NN / 1024);
    dim3 tb(32, 8);
    dim3 gp(DDIM / 128, MTOT / 128, 1);

    // merged prep: split q (z=0), split k (z=1), convert v (z=2)
    prep_inputs<<<dim3(splitBlocks, 1, 3), 256>>>(queries, keys, values,
                                                  iqkh, iqkl, ivh);
    // merged weight transposes (lo only for Wq, Wk)
    tweights<<<dim3(32, 32, 5), tb>>>(Wq, Wk, Wv, Wg, Wo, wt);

    // q+k projections — 3-pass, merged: z strides select q(0)/k(1)
    gemm3<0,2><<<dim3(DDIM / 128, MTOT / 128, 2), 256, GEMM_SMEM>>>(
        iqkh, iqkl, wth[0], wtl[0],
        (long long)NN, (long long)(2 * WSZ), DDIM,
        nullptr, qkh, qkl, DDIM, (long long)NN,
        bq, nullptr, (long long)(bk - bq));

    // v+gate projections — 1-pass, merged: z=0 v (plain), z=1 gate (sigmoid)
    gemm3<3,6><<<dim3(DDIM / 128, MTOT / 128, 2), 256, GEMM_SMEM>>>(
        ivh, ivh, wth[2], wth[2],
        (long long)(iqkh - ivh), (long long)(2 * WSZ), DDIM,
        nullptr, vg, nullptr, DDIM, (long long)NN,
        bv, nullptr, (long long)(bg - bv));

    // scores = q @ k^T (per batch) — 3-pass
    gemm3<0,0><<<dim3(SEQ / 128, SEQ / 128, BB), 256, GEMM_SMEM>>>(
        qkh, qkl, qkh + NN, qkl + NN,
        (long long)SEQ * DDIM, (long long)SEQ * DDIM, DDIM,
        sc, nullptr, nullptr, SEQ, (long long)SEQ * SEQ, nullptr, nullptr, 0);

    // softmax -> fp16 P
    softmax_p<<<MTOT, 256>>>(sc, ph);

    // transpose v per batch: fp16 [S,D] -> [D,S]
    transpose_h16<<<dim3(DDIM / 32, SEQ / 32, BB), tb>>>(
        vg, vth, SEQ, DDIM, (long long)SEQ * DDIM, (long long)SEQ * DDIM);

    // context = (P @ v) * gate -> fp16; 1-pass
    gemm3<3,5><<<dim3(DDIM / 128, SEQ / 128, BB), 256, GEMM_SMEM>>>(
        ph, ph, vth, vth, (long long)SEQ * SEQ, (long long)DDIM * SEQ, SEQ,
        nullptr, ch, nullptr, DDIM, (long long)SEQ * DDIM,
        nullptr, vg + NN, (long long)SEQ * DDIM);

    // out = ctx @ Wo + bo — 1-pass
    gemm3<3,1><<<gp, 256, GEMM_SMEM>>>(ch, ch, wth[4], wth[4], 0, 0, DDIM,
                                       out, nullptr, nullptr, DDIM, 0, bo, nullptr, 0);
}